// round 5
// baseline (speedup 1.0000x reference)
#include <cuda_runtime.h>
#include <math.h>

#define Bz 64
#define Tz 512
#define INz 1024
#define Hz 1024
#define Cz 512

#define RBLOCKS 128
#define RTHREADS 256

// ---------------- persistent scratch ----------------------------------------
__device__ float d_xc[(size_t)Bz * Tz * Cz];          // xc, then c (in-place)
__device__ float d_g[(size_t)Bz * Tz * Hz];           // g = c @ Uc^T
__device__ float d_part[(size_t)RBLOCKS * 64 * 128];  // per-step partials
__device__ float d_hTr[Hz * Bz];                      // h transposed [n][m]
__device__ unsigned d_gcount;                         // grid barrier counter

// ---------------- init: transpose h0, reset barrier -------------------------
__global__ void init_kernel(const float* __restrict__ h0) {
    int idx = blockIdx.x * blockDim.x + threadIdx.x;
    if (idx == 0) d_gcount = 0u;
    if (idx < Hz * Bz) {
        int n = idx >> 6, m = idx & 63;
        d_hTr[idx] = h0[m * Hz + n];
    }
}

// ---------------- EMA scan over T (in-place xc -> c), emit c_T --------------
__global__ void scan_kernel(const float* __restrict__ c0, float* __restrict__ outCT) {
    int idx = blockIdx.x * blockDim.x + threadIdx.x;   // 0 .. B*C-1
    int b = idx >> 9;
    int ch = idx & 511;
    float c = c0[idx];
    float* p = d_xc + (size_t)b * Tz * Cz + ch;
    const float a = 0.95f, na = 0.05f;
#pragma unroll 4
    for (int t = 0; t < Tz; ++t) {
        float v = p[t * Cz];
        c = na * c + a * v;
        p[t * Cz] = c;
    }
    outCT[idx] = c;
}

// ---------------- fp32 SGEMM:  C[M,N] = A[M,K] @ Bw[N,K]^T (+ bias) ---------
// block tile 128x128, 256 threads, 8x8 per-thread tile, K-chunk 16,
// double-buffered SMEM: 1 __syncthreads per chunk, LDG overlapped with compute
__global__ __launch_bounds__(256, 2) void sgemm_tn(
    const float* __restrict__ A, const float* __restrict__ Bw,
    const float* __restrict__ bias, float* __restrict__ Cout,
    int N, int K)
{
    __shared__ float As[2][16][132];
    __shared__ float Bs[2][16][132];
    const int tid = threadIdx.x;
    const int tx = tid & 15, ty = tid >> 4;
    const int m0 = blockIdx.x * 128, n0 = blockIdx.y * 128;
    const int lrow = tid >> 2;          // 0..63
    const int lkq  = (tid & 3) << 2;    // 0,4,8,12

    const float* Aptr0 = &A[(size_t)(m0 + lrow) * K + lkq];
    const float* Aptr1 = &A[(size_t)(m0 + lrow + 64) * K + lkq];
    const float* Bptr0 = &Bw[(size_t)(n0 + lrow) * K + lkq];
    const float* Bptr1 = &Bw[(size_t)(n0 + lrow + 64) * K + lkq];

    float acc[8][8];
#pragma unroll
    for (int i = 0; i < 8; ++i)
#pragma unroll
        for (int j = 0; j < 8; ++j) acc[i][j] = 0.f;

    // prologue: stage chunk 0 into buffer 0
    {
        float4 va0 = *reinterpret_cast<const float4*>(Aptr0);
        float4 va1 = *reinterpret_cast<const float4*>(Aptr1);
        float4 vb0 = *reinterpret_cast<const float4*>(Bptr0);
        float4 vb1 = *reinterpret_cast<const float4*>(Bptr1);
        As[0][lkq + 0][lrow] = va0.x; As[0][lkq + 1][lrow] = va0.y;
        As[0][lkq + 2][lrow] = va0.z; As[0][lkq + 3][lrow] = va0.w;
        As[0][lkq + 0][lrow + 64] = va1.x; As[0][lkq + 1][lrow + 64] = va1.y;
        As[0][lkq + 2][lrow + 64] = va1.z; As[0][lkq + 3][lrow + 64] = va1.w;
        Bs[0][lkq + 0][lrow] = vb0.x; Bs[0][lkq + 1][lrow] = vb0.y;
        Bs[0][lkq + 2][lrow] = vb0.z; Bs[0][lkq + 3][lrow] = vb0.w;
        Bs[0][lkq + 0][lrow + 64] = vb1.x; Bs[0][lkq + 1][lrow + 64] = vb1.y;
        Bs[0][lkq + 2][lrow + 64] = vb1.z; Bs[0][lkq + 3][lrow + 64] = vb1.w;
    }
    __syncthreads();

    const int nchunk = K >> 4;
    for (int c = 0; c < nchunk; ++c) {
        const int cur = c & 1, nxt = cur ^ 1;
        float4 va0, va1, vb0, vb1;
        const bool more = (c + 1 < nchunk);
        if (more) {
            int off = (c + 1) * 16;
            va0 = *reinterpret_cast<const float4*>(Aptr0 + off);
            va1 = *reinterpret_cast<const float4*>(Aptr1 + off);
            vb0 = *reinterpret_cast<const float4*>(Bptr0 + off);
            vb1 = *reinterpret_cast<const float4*>(Bptr1 + off);
        }
#pragma unroll
        for (int k = 0; k < 16; ++k) {
            float4 a0 = *reinterpret_cast<const float4*>(&As[cur][k][ty * 4]);
            float4 a1 = *reinterpret_cast<const float4*>(&As[cur][k][ty * 4 + 64]);
            float4 b0 = *reinterpret_cast<const float4*>(&Bs[cur][k][tx * 4]);
            float4 b1 = *reinterpret_cast<const float4*>(&Bs[cur][k][tx * 4 + 64]);
            float am[8] = {a0.x, a0.y, a0.z, a0.w, a1.x, a1.y, a1.z, a1.w};
            float bn[8] = {b0.x, b0.y, b0.z, b0.w, b1.x, b1.y, b1.z, b1.w};
#pragma unroll
            for (int i = 0; i < 8; ++i)
#pragma unroll
                for (int j = 0; j < 8; ++j)
                    acc[i][j] = fmaf(am[i], bn[j], acc[i][j]);
        }
        if (more) {
            As[nxt][lkq + 0][lrow] = va0.x; As[nxt][lkq + 1][lrow] = va0.y;
            As[nxt][lkq + 2][lrow] = va0.z; As[nxt][lkq + 3][lrow] = va0.w;
            As[nxt][lkq + 0][lrow + 64] = va1.x; As[nxt][lkq + 1][lrow + 64] = va1.y;
            As[nxt][lkq + 2][lrow + 64] = va1.z; As[nxt][lkq + 3][lrow + 64] = va1.w;
            Bs[nxt][lkq + 0][lrow] = vb0.x; Bs[nxt][lkq + 1][lrow] = vb0.y;
            Bs[nxt][lkq + 2][lrow] = vb0.z; Bs[nxt][lkq + 3][lrow] = vb0.w;
            Bs[nxt][lkq + 0][lrow + 64] = vb1.x; Bs[nxt][lkq + 1][lrow + 64] = vb1.y;
            Bs[nxt][lkq + 2][lrow + 64] = vb1.z; Bs[nxt][lkq + 3][lrow + 64] = vb1.w;
        }
        __syncthreads();
    }

    float bv[8] = {0.f, 0.f, 0.f, 0.f, 0.f, 0.f, 0.f, 0.f};
    if (bias) {
#pragma unroll
        for (int j = 0; j < 4; ++j) {
            bv[j]     = bias[n0 + tx * 4 + j];
            bv[4 + j] = bias[n0 + 64 + tx * 4 + j];
        }
    }
#pragma unroll
    for (int hm = 0; hm < 2; ++hm) {
#pragma unroll
        for (int i = 0; i < 4; ++i) {
            int ii = hm * 4 + i;
            int row = m0 + hm * 64 + ty * 4 + i;
            float4 o0 = make_float4(acc[ii][0] + bv[0], acc[ii][1] + bv[1],
                                    acc[ii][2] + bv[2], acc[ii][3] + bv[3]);
            float4 o1 = make_float4(acc[ii][4] + bv[4], acc[ii][5] + bv[5],
                                    acc[ii][6] + bv[6], acc[ii][7] + bv[7]);
            *reinterpret_cast<float4*>(&Cout[(size_t)row * N + n0 + tx * 4]) = o0;
            *reinterpret_cast<float4*>(&Cout[(size_t)row * N + n0 + 64 + tx * 4]) = o1;
        }
    }
}

// ---------------- grid-wide barrier (all 128 blocks co-resident) ------------
__device__ __forceinline__ void gsync(unsigned& target) {
    __threadfence();
    __syncthreads();
    target += RBLOCKS;
    if (threadIdx.x == 0) {
        atomicAdd(&d_gcount, 1u);
        while (*(volatile unsigned*)&d_gcount < target) { __nanosleep(32); }
    }
    __syncthreads();
}

// ---------------- persistent recurrence kernel ------------------------------
// grid 128 = 8 N-tiles (128 cols) x 16 K-slices (64), 256 threads/block
__global__ __launch_bounds__(RTHREADS, 1) void recur_kernel(
    const float* __restrict__ Vh, float* __restrict__ out, float* __restrict__ outHT)
{
    __shared__ float vhs[64 * 128];   // Vh slice [k][n], resident all steps (32KB)
    __shared__ float hs[64 * 64];     // h slice  [k][m], restaged per step (16KB)

    const int tid = threadIdx.x;
    const int bid = blockIdx.x;
    const int nb = bid >> 4, kb = bid & 15;
    const int n0 = nb * 128, k0 = kb * 64;
    const int tx = tid & 15, ty = tid >> 4;   // ty 0..15 (4 m-rows), tx 0..15 (8 n-cols)

    // stage Vh slice once: vhs[k][n] = Vh[n0+n][k0+k]
    for (int it = 0; it < 32; ++it) {
        int lin = it * 256 + tid;
        int n = lin >> 6, k = lin & 63;
        vhs[k * 128 + n] = Vh[(size_t)(n0 + n) * Hz + k0 + k];
    }

    // phase-2 element assignment: 2 consecutive n per thread, m-major
    const int e0 = bid * 512 + tid * 2;
    const int pm = e0 >> 10;
    const int pn = e0 & 1023;
    const int pnb = pn >> 7, pnl = pn & 127;

    float* partW = d_part + (size_t)bid * (64 * 128);
    unsigned target = 0;
    __syncthreads();

    for (int t = 0; t < Tz; ++t) {
        // ---- phase 1: stage h slice (coalesced float4) ----
        {
            const float4* src = reinterpret_cast<const float4*>(d_hTr + (size_t)k0 * 64);
            float4* dst = reinterpret_cast<float4*>(hs);
#pragma unroll
            for (int r = 0; r < 4; ++r) {
                int i = r * 256 + tid;            // 0..1023 float4 index
                dst[i] = __ldcg(&src[i]);
            }
        }
        __syncthreads();

        float acc[4][8];
#pragma unroll
        for (int i = 0; i < 4; ++i)
#pragma unroll
            for (int j = 0; j < 8; ++j) acc[i][j] = 0.f;

#pragma unroll 8
        for (int k = 0; k < 64; ++k) {
            float4 a  = *reinterpret_cast<const float4*>(&hs[k * 64 + ty * 4]);
            float4 b0 = *reinterpret_cast<const float4*>(&vhs[k * 128 + tx * 8]);
            float4 b1 = *reinterpret_cast<const float4*>(&vhs[k * 128 + tx * 8 + 4]);
            float am[4] = {a.x, a.y, a.z, a.w};
            float bn[8] = {b0.x, b0.y, b0.z, b0.w, b1.x, b1.y, b1.z, b1.w};
#pragma unroll
            for (int i = 0; i < 4; ++i)
#pragma unroll
                for (int j = 0; j < 8; ++j)
                    acc[i][j] = fmaf(am[i], bn[j], acc[i][j]);
        }

        // write partials (L2-coherent)
#pragma unroll
        for (int i = 0; i < 4; ++i) {
            int m = ty * 4 + i;
            __stcg(reinterpret_cast<float4*>(&partW[m * 128 + tx * 8]),
                   make_float4(acc[i][0], acc[i][1], acc[i][2], acc[i][3]));
            __stcg(reinterpret_cast<float4*>(&partW[m * 128 + tx * 8 + 4]),
                   make_float4(acc[i][4], acc[i][5], acc[i][6], acc[i][7]));
        }

        gsync(target);   // partials visible

        // ---- phase 2: reduce 16 partials + g_t, tanh, scatter h ----
        float2 s = *reinterpret_cast<const float2*>(&d_g[((size_t)pm * Tz + t) * Hz + pn]);
#pragma unroll
        for (int k2 = 0; k2 < 16; ++k2) {
            float2 p = __ldcg(reinterpret_cast<const float2*>(
                &d_part[(size_t)(pnb * 16 + k2) * (64 * 128) + pm * 128 + pnl]));
            s.x += p.x; s.y += p.y;
        }
        float2 hv = make_float2(tanhf(s.x), tanhf(s.y));

        *reinterpret_cast<float2*>(&out[((size_t)pm * Tz + t) * Hz + pn]) = hv;
        __stcg(&d_hTr[(pn + 0) * 64 + pm], hv.x);
        __stcg(&d_hTr[(pn + 1) * 64 + pm], hv.y);
        if (t == Tz - 1) {
            *reinterpret_cast<float2*>(&outHT[(size_t)pm * Hz + pn]) = hv;
        }

        gsync(target);   // h ready for next step
    }
}

// ---------------- launch ----------------------------------------------------
extern "C" void kernel_launch(void* const* d_in, const int* in_sizes, int n_in,
                              void* d_out, int out_size) {
    const float* x  = (const float*)d_in[0];
    const float* h0 = (const float*)d_in[1];
    const float* c0 = (const float*)d_in[2];
    const float* Wx = (const float*)d_in[3];
    const float* bx = (const float*)d_in[4];
    const float* Uc = (const float*)d_in[5];
    const float* Vh = (const float*)d_in[6];

    float* out   = (float*)d_out;                       // [B,T,H]
    float* outHT = out + (size_t)Bz * Tz * Hz;          // [B,H]
    float* outCT = outHT + (size_t)Bz * Hz;             // [B,C]

    float *dxc, *dg;
    cudaGetSymbolAddress((void**)&dxc, d_xc);
    cudaGetSymbolAddress((void**)&dg, d_g);

    // 1) init: transpose h0, reset barrier
    init_kernel<<<(Hz * Bz + 255) / 256, 256>>>(h0);

    // 2) xc = x @ Wx^T + bx   (M=32768, N=512, K=1024)
    sgemm_tn<<<dim3((Bz * Tz) / 128, Cz / 128), 256>>>(x, Wx, bx, dxc, Cz, INz);

    // 3) EMA scan: xc -> c (in place), write c_T
    scan_kernel<<<(Bz * Cz) / 256, 256>>>(c0, outCT);

    // 4) g = c @ Uc^T   (M=32768, N=1024, K=512)
    sgemm_tn<<<dim3((Bz * Tz) / 128, Hz / 128), 256>>>(dxc, Uc, nullptr, dg, Hz, Cz);

    // 5) recurrence: h_t = tanh(g_t + h_{t-1} @ Vh^T), all 512 steps in one launch
    recur_kernel<<<RBLOCKS, RTHREADS>>>(Vh, out, outHT);
}

// round 7
// speedup vs baseline: 1.1728x; 1.1728x over previous
#include <cuda_runtime.h>
#include <math.h>
#include <stdint.h>

#define Bz 64
#define Tz 512
#define INz 1024
#define Hz 1024
#define Cz 512

#define RBLOCKS 128
#define RTHREADS 128

typedef unsigned long long ull;

// ---------------- persistent scratch ----------------------------------------
__device__ float d_xc[(size_t)Bz * Tz * Cz];          // xc, then c (in-place)
__device__ float d_g[(size_t)Bz * Tz * Hz];           // g = c @ Uc^T
__device__ float d_part[(size_t)RBLOCKS * 64 * 128];  // per-step partials
__device__ float d_hTr[Hz * 128];                     // h transposed + DUPLICATED [n][2m]
__device__ unsigned d_gcount;                         // grid barrier counter

// ---------------- f32x2 helpers ---------------------------------------------
__device__ __forceinline__ uint32_t saddr(const void* p) {
    return (uint32_t)__cvta_generic_to_shared(p);
}
__device__ __forceinline__ void lds2(ull& a, ull& b, uint32_t addr) {
    asm volatile("ld.shared.v2.u64 {%0,%1}, [%2];" : "=l"(a), "=l"(b) : "r"(addr));
}
__device__ __forceinline__ void ffma2(ull& d, ull a, ull b) {
    asm("fma.rn.f32x2 %0, %1, %2, %0;" : "+l"(d) : "l"(a), "l"(b));
}
__device__ __forceinline__ float2 u2f(ull v) {
    float2 r; asm("mov.b64 {%0,%1}, %2;" : "=f"(r.x), "=f"(r.y) : "l"(v)); return r;
}

// ---------------- init: transpose+dup h0, reset barrier ----------------------
__global__ void init_kernel(const float* __restrict__ h0) {
    int idx = blockIdx.x * blockDim.x + threadIdx.x;   // 0 .. Hz*Bz-1
    if (idx == 0) d_gcount = 0u;
    if (idx < Hz * Bz) {
        int n = idx >> 6, m = idx & 63;
        float v = h0[m * Hz + n];
        *reinterpret_cast<float2*>(&d_hTr[n * 128 + 2 * m]) = make_float2(v, v);
    }
}

// ---------------- EMA scan over T (in-place xc -> c), emit c_T --------------
__global__ void scan_kernel(const float* __restrict__ c0, float* __restrict__ outCT) {
    int idx = blockIdx.x * blockDim.x + threadIdx.x;   // 0 .. B*C-1
    int b = idx >> 9;
    int ch = idx & 511;
    float c = c0[idx];
    float* p = d_xc + (size_t)b * Tz * Cz + ch;
    const float a = 0.95f, na = 0.05f;
#pragma unroll 4
    for (int t = 0; t < Tz; ++t) {
        float v = p[t * Cz];
        c = na * c + a * v;
        p[t * Cz] = c;
    }
    outCT[idx] = c;
}

// ---------------- fp32 SGEMM (R4 proven): double-buffered, 128x128 ----------
__global__ __launch_bounds__(256, 2) void sgemm_tn(
    const float* __restrict__ A, const float* __restrict__ Bw,
    const float* __restrict__ bias, float* __restrict__ Cout,
    int N, int K)
{
    __shared__ float As[2][16][132];
    __shared__ float Bs[2][16][132];
    const int tid = threadIdx.x;
    const int tx = tid & 15, ty = tid >> 4;
    const int m0 = blockIdx.x * 128, n0 = blockIdx.y * 128;
    const int lrow = tid >> 2;
    const int lkq  = (tid & 3) << 2;

    const float* Aptr0 = &A[(size_t)(m0 + lrow) * K + lkq];
    const float* Aptr1 = &A[(size_t)(m0 + lrow + 64) * K + lkq];
    const float* Bptr0 = &Bw[(size_t)(n0 + lrow) * K + lkq];
    const float* Bptr1 = &Bw[(size_t)(n0 + lrow + 64) * K + lkq];

    float acc[8][8];
#pragma unroll
    for (int i = 0; i < 8; ++i)
#pragma unroll
        for (int j = 0; j < 8; ++j) acc[i][j] = 0.f;

    {
        float4 va0 = *reinterpret_cast<const float4*>(Aptr0);
        float4 va1 = *reinterpret_cast<const float4*>(Aptr1);
        float4 vb0 = *reinterpret_cast<const float4*>(Bptr0);
        float4 vb1 = *reinterpret_cast<const float4*>(Bptr1);
        As[0][lkq + 0][lrow] = va0.x; As[0][lkq + 1][lrow] = va0.y;
        As[0][lkq + 2][lrow] = va0.z; As[0][lkq + 3][lrow] = va0.w;
        As[0][lkq + 0][lrow + 64] = va1.x; As[0][lkq + 1][lrow + 64] = va1.y;
        As[0][lkq + 2][lrow + 64] = va1.z; As[0][lkq + 3][lrow + 64] = va1.w;
        Bs[0][lkq + 0][lrow] = vb0.x; Bs[0][lkq + 1][lrow] = vb0.y;
        Bs[0][lkq + 2][lrow] = vb0.z; Bs[0][lkq + 3][lrow] = vb0.w;
        Bs[0][lkq + 0][lrow + 64] = vb1.x; Bs[0][lkq + 1][lrow + 64] = vb1.y;
        Bs[0][lkq + 2][lrow + 64] = vb1.z; Bs[0][lkq + 3][lrow + 64] = vb1.w;
    }
    __syncthreads();

    const int nchunk = K >> 4;
    for (int c = 0; c < nchunk; ++c) {
        const int cur = c & 1, nxt = cur ^ 1;
        float4 va0, va1, vb0, vb1;
        const bool more = (c + 1 < nchunk);
        if (more) {
            int off = (c + 1) * 16;
            va0 = *reinterpret_cast<const float4*>(Aptr0 + off);
            va1 = *reinterpret_cast<const float4*>(Aptr1 + off);
            vb0 = *reinterpret_cast<const float4*>(Bptr0 + off);
            vb1 = *reinterpret_cast<const float4*>(Bptr1 + off);
        }
#pragma unroll
        for (int k = 0; k < 16; ++k) {
            float4 a0 = *reinterpret_cast<const float4*>(&As[cur][k][ty * 4]);
            float4 a1 = *reinterpret_cast<const float4*>(&As[cur][k][ty * 4 + 64]);
            float4 b0 = *reinterpret_cast<const float4*>(&Bs[cur][k][tx * 4]);
            float4 b1 = *reinterpret_cast<const float4*>(&Bs[cur][k][tx * 4 + 64]);
            float am[8] = {a0.x, a0.y, a0.z, a0.w, a1.x, a1.y, a1.z, a1.w};
            float bn[8] = {b0.x, b0.y, b0.z, b0.w, b1.x, b1.y, b1.z, b1.w};
#pragma unroll
            for (int i = 0; i < 8; ++i)
#pragma unroll
                for (int j = 0; j < 8; ++j)
                    acc[i][j] = fmaf(am[i], bn[j], acc[i][j]);
        }
        if (more) {
            As[nxt][lkq + 0][lrow] = va0.x; As[nxt][lkq + 1][lrow] = va0.y;
            As[nxt][lkq + 2][lrow] = va0.z; As[nxt][lkq + 3][lrow] = va0.w;
            As[nxt][lkq + 0][lrow + 64] = va1.x; As[nxt][lkq + 1][lrow + 64] = va1.y;
            As[nxt][lkq + 2][lrow + 64] = va1.z; As[nxt][lkq + 3][lrow + 64] = va1.w;
            Bs[nxt][lkq + 0][lrow] = vb0.x; Bs[nxt][lkq + 1][lrow] = vb0.y;
            Bs[nxt][lkq + 2][lrow] = vb0.z; Bs[nxt][lkq + 3][lrow] = vb0.w;
            Bs[nxt][lkq + 0][lrow + 64] = vb1.x; Bs[nxt][lkq + 1][lrow + 64] = vb1.y;
            Bs[nxt][lkq + 2][lrow + 64] = vb1.z; Bs[nxt][lkq + 3][lrow + 64] = vb1.w;
        }
        __syncthreads();
    }

    float bv[8] = {0.f, 0.f, 0.f, 0.f, 0.f, 0.f, 0.f, 0.f};
    if (bias) {
#pragma unroll
        for (int j = 0; j < 4; ++j) {
            bv[j]     = bias[n0 + tx * 4 + j];
            bv[4 + j] = bias[n0 + 64 + tx * 4 + j];
        }
    }
#pragma unroll
    for (int hm = 0; hm < 2; ++hm) {
#pragma unroll
        for (int i = 0; i < 4; ++i) {
            int ii = hm * 4 + i;
            int row = m0 + hm * 64 + ty * 4 + i;
            float4 o0 = make_float4(acc[ii][0] + bv[0], acc[ii][1] + bv[1],
                                    acc[ii][2] + bv[2], acc[ii][3] + bv[3]);
            float4 o1 = make_float4(acc[ii][4] + bv[4], acc[ii][5] + bv[5],
                                    acc[ii][6] + bv[6], acc[ii][7] + bv[7]);
            *reinterpret_cast<float4*>(&Cout[(size_t)row * N + n0 + tx * 4]) = o0;
            *reinterpret_cast<float4*>(&Cout[(size_t)row * N + n0 + 64 + tx * 4]) = o1;
        }
    }
}

// ---------------- grid-wide barrier (all 128 blocks co-resident) ------------
__device__ __forceinline__ void gsync(unsigned& target) {
    __threadfence();
    __syncthreads();
    target += RBLOCKS;
    if (threadIdx.x == 0) {
        atomicAdd(&d_gcount, 1u);
        while (*(volatile unsigned*)&d_gcount < target) { __nanosleep(32); }
    }
    __syncthreads();
}

// ---------------- persistent recurrence: 128 thr, 8x8 tile, FFMA2 core ------
// grid 128 = 8 N-tiles (128 cols) x 16 K-slices (64)
__global__ __launch_bounds__(RTHREADS, 1) void recur_kernel(
    const float* __restrict__ Vh, float* __restrict__ out, float* __restrict__ outHT)
{
    extern __shared__ float dynsm[];
    float* vhs = dynsm;               // [64][128]  Vh slice [k][n] (32KB, resident)
    float* hsD = dynsm + 64 * 128;    // [64][128]  h slice duplicated [k][2m] (32KB)

    const int tid = threadIdx.x;
    const int bid = blockIdx.x;
    const int nb = bid >> 4, kb = bid & 15;
    const int n0 = nb * 128, k0 = kb * 64;
    const int tx = tid & 15, ty = tid >> 4;   // ty 0..7, tx 0..15

    for (int it = 0; it < 64; ++it) {
        int lin = it * 128 + tid;
        int n = lin >> 6, k = lin & 63;
        vhs[k * 128 + n] = Vh[(size_t)(n0 + n) * Hz + k0 + k];
    }

    const int e0 = bid * 512 + tid * 4;
    const int pm = e0 >> 10;
    const int pn = e0 & 1023;
    const int pnb = pn >> 7, pnl = pn & 127;

    float* partW = d_part + (size_t)bid * (64 * 128);
    unsigned target = 0;
    __syncthreads();

    for (int t = 0; t < Tz; ++t) {
        // ---- phase 1: stage duplicated h slice (plain coalesced copy) ----
        {
            const float4* src = reinterpret_cast<const float4*>(d_hTr + (size_t)k0 * 128);
            float4* dst = reinterpret_cast<float4*>(hsD);
#pragma unroll
            for (int r = 0; r < 16; ++r) {
                int i = r * 128 + tid;
                dst[i] = __ldcg(&src[i]);
            }
        }
        __syncthreads();

        ull acc[8][4];
#pragma unroll
        for (int i = 0; i < 8; ++i)
#pragma unroll
            for (int j = 0; j < 4; ++j) acc[i][j] = 0ull;

#pragma unroll 8
        for (int k = 0; k < 64; ++k) {
            ull a[8], b[4];
            lds2(a[0], a[1], saddr(&hsD[k * 128 + ty * 8]));
            lds2(a[2], a[3], saddr(&hsD[k * 128 + ty * 8 + 4]));
            lds2(a[4], a[5], saddr(&hsD[k * 128 + 64 + ty * 8]));
            lds2(a[6], a[7], saddr(&hsD[k * 128 + 64 + ty * 8 + 4]));
            lds2(b[0], b[1], saddr(&vhs[k * 128 + tx * 4]));
            lds2(b[2], b[3], saddr(&vhs[k * 128 + 64 + tx * 4]));
#pragma unroll
            for (int i = 0; i < 8; ++i)
#pragma unroll
                for (int j = 0; j < 4; ++j)
                    ffma2(acc[i][j], a[i], b[j]);
        }

        // write partials (L2-coherent)
#pragma unroll
        for (int i = 0; i < 8; ++i) {
            int m = (i < 4) ? (ty * 4 + i) : (32 + ty * 4 + (i - 4));
            float2 p0 = u2f(acc[i][0]), p1 = u2f(acc[i][1]);
            float2 p2 = u2f(acc[i][2]), p3 = u2f(acc[i][3]);
            __stcg(reinterpret_cast<float4*>(&partW[m * 128 + tx * 4]),
                   make_float4(p0.x, p0.y, p1.x, p1.y));
            __stcg(reinterpret_cast<float4*>(&partW[m * 128 + 64 + tx * 4]),
                   make_float4(p2.x, p2.y, p3.x, p3.y));
        }

        gsync(target);   // partials visible

        // ---- phase 2: reduce 16 partials + g_t, tanh, scatter dup h ----
        float4 s = *reinterpret_cast<const float4*>(&d_g[((size_t)pm * Tz + t) * Hz + pn]);
#pragma unroll
        for (int k2 = 0; k2 < 16; ++k2) {
            float4 p = __ldcg(reinterpret_cast<const float4*>(
                &d_part[(size_t)(pnb * 16 + k2) * (64 * 128) + pm * 128 + pnl]));
            s.x += p.x; s.y += p.y; s.z += p.z; s.w += p.w;
        }
        float4 hv = make_float4(tanhf(s.x), tanhf(s.y), tanhf(s.z), tanhf(s.w));

        *reinterpret_cast<float4*>(&out[((size_t)pm * Tz + t) * Hz + pn]) = hv;
        __stcg(reinterpret_cast<float2*>(&d_hTr[(pn + 0) * 128 + 2 * pm]), make_float2(hv.x, hv.x));
        __stcg(reinterpret_cast<float2*>(&d_hTr[(pn + 1) * 128 + 2 * pm]), make_float2(hv.y, hv.y));
        __stcg(reinterpret_cast<float2*>(&d_hTr[(pn + 2) * 128 + 2 * pm]), make_float2(hv.z, hv.z));
        __stcg(reinterpret_cast<float2*>(&d_hTr[(pn + 3) * 128 + 2 * pm]), make_float2(hv.w, hv.w));
        if (t == Tz - 1) {
            *reinterpret_cast<float4*>(&outHT[(size_t)pm * Hz + pn]) = hv;
        }

        gsync(target);   // h ready for next step
    }
}

// ---------------- launch ----------------------------------------------------
extern "C" void kernel_launch(void* const* d_in, const int* in_sizes, int n_in,
                              void* d_out, int out_size) {
    const float* x  = (const float*)d_in[0];
    const float* h0 = (const float*)d_in[1];
    const float* c0 = (const float*)d_in[2];
    const float* Wx = (const float*)d_in[3];
    const float* bx = (const float*)d_in[4];
    const float* Uc = (const float*)d_in[5];
    const float* Vh = (const float*)d_in[6];

    float* out   = (float*)d_out;                       // [B,T,H]
    float* outHT = out + (size_t)Bz * Tz * Hz;          // [B,H]
    float* outCT = outHT + (size_t)Bz * Hz;             // [B,C]

    float *dxc, *dg;
    cudaGetSymbolAddress((void**)&dxc, d_xc);
    cudaGetSymbolAddress((void**)&dg, d_g);

    static bool attr_set = false;
    if (!attr_set) {
        cudaFuncSetAttribute(recur_kernel,
                             cudaFuncAttributeMaxDynamicSharedMemorySize, 65536);
        attr_set = true;
    }

    // 1) init: transpose+dup h0, reset barrier
    init_kernel<<<(Hz * Bz + 255) / 256, 256>>>(h0);

    // 2) xc = x @ Wx^T + bx   (M=32768, N=512, K=1024)
    sgemm_tn<<<dim3((Bz * Tz) / 128, Cz / 128), 256>>>(x, Wx, bx, dxc, Cz, INz);

    // 3) EMA scan: xc -> c (in place), write c_T
    scan_kernel<<<(Bz * Cz) / 256, 256>>>(c0, outCT);

    // 4) g = c @ Uc^T   (M=32768, N=1024, K=512)
    sgemm_tn<<<dim3((Bz * Tz) / 128, Hz / 128), 256>>>(dxc, Uc, nullptr, dg, Hz, Cz);

    // 5) recurrence: h_t = tanh(g_t + h_{t-1} @ Vh^T), all 512 steps
    recur_kernel<<<RBLOCKS, RTHREADS, 65536>>>(Vh, out, outHT);
}

// round 8
// speedup vs baseline: 1.2357x; 1.0537x over previous
#include <cuda_runtime.h>
#include <math.h>
#include <stdint.h>

#define Bz 64
#define Tz 512
#define INz 1024
#define Hz 1024
#define Cz 512

#define RBLOCKS 128
#define RTHREADS 128

typedef unsigned long long ull;

// ---------------- persistent scratch ----------------------------------------
__device__ float d_xc[(size_t)Bz * Tz * Cz];          // xc, then c (in-place)
__device__ float d_g[(size_t)Bz * Tz * Hz];           // g = c @ Uc^T
__device__ float d_part[(size_t)RBLOCKS * 64 * 128];  // per-step partials
__device__ float d_hTr[Hz * 64];                      // h transposed [n][m]
__device__ unsigned d_gcount;                         // grid barrier counter

// ---------------- f32x2 helpers ---------------------------------------------
__device__ __forceinline__ uint32_t saddr(const void* p) {
    return (uint32_t)__cvta_generic_to_shared(p);
}
__device__ __forceinline__ void lds2(ull& a, ull& b, uint32_t addr) {
    asm volatile("ld.shared.v2.u64 {%0,%1}, [%2];" : "=l"(a), "=l"(b) : "r"(addr));
}
__device__ __forceinline__ void ffma2(ull& d, ull a, ull b) {
    asm("fma.rn.f32x2 %0, %1, %2, %0;" : "+l"(d) : "l"(a), "l"(b));
}
__device__ __forceinline__ float2 u2f(ull v) {
    float2 r; asm("mov.b64 {%0,%1}, %2;" : "=f"(r.x), "=f"(r.y) : "l"(v)); return r;
}
__device__ __forceinline__ ull dup2(float f) {
    ull d; asm("mov.b64 %0, {%1,%1};" : "=l"(d) : "f"(f)); return d;
}

// ---------------- init: transpose h0, reset barrier -------------------------
__global__ void init_kernel(const float* __restrict__ h0) {
    int idx = blockIdx.x * blockDim.x + threadIdx.x;   // 0 .. Hz*Bz-1
    if (idx == 0) d_gcount = 0u;
    if (idx < Hz * Bz) {
        int n = idx >> 6, m = idx & 63;
        d_hTr[n * 64 + m] = h0[m * Hz + n];
    }
}

// ---------------- EMA scan over T (in-place xc -> c), emit c_T --------------
__global__ void scan_kernel(const float* __restrict__ c0, float* __restrict__ outCT) {
    int idx = blockIdx.x * blockDim.x + threadIdx.x;   // 0 .. B*C-1
    int b = idx >> 9;
    int ch = idx & 511;
    float c = c0[idx];
    float* p = d_xc + (size_t)b * Tz * Cz + ch;
    const float a = 0.95f, na = 0.05f;
#pragma unroll 8
    for (int t = 0; t < Tz; ++t) {
        float v = p[t * Cz];
        c = na * c + a * v;
        p[t * Cz] = c;
    }
    outCT[idx] = c;
}

// ---------------- fp32 SGEMM (R4 proven): double-buffered, 128x128 ----------
__global__ __launch_bounds__(256, 2) void sgemm_tn(
    const float* __restrict__ A, const float* __restrict__ Bw,
    const float* __restrict__ bias, float* __restrict__ Cout,
    int N, int K)
{
    __shared__ float As[2][16][132];
    __shared__ float Bs[2][16][132];
    const int tid = threadIdx.x;
    const int tx = tid & 15, ty = tid >> 4;
    const int m0 = blockIdx.x * 128, n0 = blockIdx.y * 128;
    const int lrow = tid >> 2;
    const int lkq  = (tid & 3) << 2;

    const float* Aptr0 = &A[(size_t)(m0 + lrow) * K + lkq];
    const float* Aptr1 = &A[(size_t)(m0 + lrow + 64) * K + lkq];
    const float* Bptr0 = &Bw[(size_t)(n0 + lrow) * K + lkq];
    const float* Bptr1 = &Bw[(size_t)(n0 + lrow + 64) * K + lkq];

    float acc[8][8];
#pragma unroll
    for (int i = 0; i < 8; ++i)
#pragma unroll
        for (int j = 0; j < 8; ++j) acc[i][j] = 0.f;

    {
        float4 va0 = *reinterpret_cast<const float4*>(Aptr0);
        float4 va1 = *reinterpret_cast<const float4*>(Aptr1);
        float4 vb0 = *reinterpret_cast<const float4*>(Bptr0);
        float4 vb1 = *reinterpret_cast<const float4*>(Bptr1);
        As[0][lkq + 0][lrow] = va0.x; As[0][lkq + 1][lrow] = va0.y;
        As[0][lkq + 2][lrow] = va0.z; As[0][lkq + 3][lrow] = va0.w;
        As[0][lkq + 0][lrow + 64] = va1.x; As[0][lkq + 1][lrow + 64] = va1.y;
        As[0][lkq + 2][lrow + 64] = va1.z; As[0][lkq + 3][lrow + 64] = va1.w;
        Bs[0][lkq + 0][lrow] = vb0.x; Bs[0][lkq + 1][lrow] = vb0.y;
        Bs[0][lkq + 2][lrow] = vb0.z; Bs[0][lkq + 3][lrow] = vb0.w;
        Bs[0][lkq + 0][lrow + 64] = vb1.x; Bs[0][lkq + 1][lrow + 64] = vb1.y;
        Bs[0][lkq + 2][lrow + 64] = vb1.z; Bs[0][lkq + 3][lrow + 64] = vb1.w;
    }
    __syncthreads();

    const int nchunk = K >> 4;
    for (int c = 0; c < nchunk; ++c) {
        const int cur = c & 1, nxt = cur ^ 1;
        float4 va0, va1, vb0, vb1;
        const bool more = (c + 1 < nchunk);
        if (more) {
            int off = (c + 1) * 16;
            va0 = *reinterpret_cast<const float4*>(Aptr0 + off);
            va1 = *reinterpret_cast<const float4*>(Aptr1 + off);
            vb0 = *reinterpret_cast<const float4*>(Bptr0 + off);
            vb1 = *reinterpret_cast<const float4*>(Bptr1 + off);
        }
#pragma unroll
        for (int k = 0; k < 16; ++k) {
            float4 a0 = *reinterpret_cast<const float4*>(&As[cur][k][ty * 4]);
            float4 a1 = *reinterpret_cast<const float4*>(&As[cur][k][ty * 4 + 64]);
            float4 b0 = *reinterpret_cast<const float4*>(&Bs[cur][k][tx * 4]);
            float4 b1 = *reinterpret_cast<const float4*>(&Bs[cur][k][tx * 4 + 64]);
            float am[8] = {a0.x, a0.y, a0.z, a0.w, a1.x, a1.y, a1.z, a1.w};
            float bn[8] = {b0.x, b0.y, b0.z, b0.w, b1.x, b1.y, b1.z, b1.w};
#pragma unroll
            for (int i = 0; i < 8; ++i)
#pragma unroll
                for (int j = 0; j < 8; ++j)
                    acc[i][j] = fmaf(am[i], bn[j], acc[i][j]);
        }
        if (more) {
            As[nxt][lkq + 0][lrow] = va0.x; As[nxt][lkq + 1][lrow] = va0.y;
            As[nxt][lkq + 2][lrow] = va0.z; As[nxt][lkq + 3][lrow] = va0.w;
            As[nxt][lkq + 0][lrow + 64] = va1.x; As[nxt][lkq + 1][lrow + 64] = va1.y;
            As[nxt][lkq + 2][lrow + 64] = va1.z; As[nxt][lkq + 3][lrow + 64] = va1.w;
            Bs[nxt][lkq + 0][lrow] = vb0.x; Bs[nxt][lkq + 1][lrow] = vb0.y;
            Bs[nxt][lkq + 2][lrow] = vb0.z; Bs[nxt][lkq + 3][lrow] = vb0.w;
            Bs[nxt][lkq + 0][lrow + 64] = vb1.x; Bs[nxt][lkq + 1][lrow + 64] = vb1.y;
            Bs[nxt][lkq + 2][lrow + 64] = vb1.z; Bs[nxt][lkq + 3][lrow + 64] = vb1.w;
        }
        __syncthreads();
    }

    float bv[8] = {0.f, 0.f, 0.f, 0.f, 0.f, 0.f, 0.f, 0.f};
    if (bias) {
#pragma unroll
        for (int j = 0; j < 4; ++j) {
            bv[j]     = bias[n0 + tx * 4 + j];
            bv[4 + j] = bias[n0 + 64 + tx * 4 + j];
        }
    }
#pragma unroll
    for (int hm = 0; hm < 2; ++hm) {
#pragma unroll
        for (int i = 0; i < 4; ++i) {
            int ii = hm * 4 + i;
            int row = m0 + hm * 64 + ty * 4 + i;
            float4 o0 = make_float4(acc[ii][0] + bv[0], acc[ii][1] + bv[1],
                                    acc[ii][2] + bv[2], acc[ii][3] + bv[3]);
            float4 o1 = make_float4(acc[ii][4] + bv[4], acc[ii][5] + bv[5],
                                    acc[ii][6] + bv[6], acc[ii][7] + bv[7]);
            *reinterpret_cast<float4*>(&Cout[(size_t)row * N + n0 + tx * 4]) = o0;
            *reinterpret_cast<float4*>(&Cout[(size_t)row * N + n0 + 64 + tx * 4]) = o1;
        }
    }
}

// ---------------- grid-wide barrier (all 128 blocks co-resident) ------------
__device__ __forceinline__ void gsync(unsigned& target) {
    __threadfence();
    __syncthreads();
    target += RBLOCKS;
    if (threadIdx.x == 0) {
        atomicAdd(&d_gcount, 1u);
        while (*(volatile unsigned*)&d_gcount < target) { __nanosleep(32); }
    }
    __syncthreads();
}

// ---------------- persistent recurrence: m-paired FFMA2 core ----------------
// grid 128 = 8 N-tiles (128 cols) x 16 K-slices (64), 128 threads/block
__global__ __launch_bounds__(RTHREADS, 1) void recur_kernel(
    const float* __restrict__ Vh, float* __restrict__ out, float* __restrict__ outHT)
{
    __shared__ float vhs[64 * 128];   // Vh slice [k][n] (32KB, resident all steps)
    __shared__ float hs[64 * 64];     // h slice  [k][m] (16KB, restaged per step)

    const int tid = threadIdx.x;
    const int bid = blockIdx.x;
    const int nb = bid >> 4, kb = bid & 15;
    const int n0 = nb * 128, k0 = kb * 64;
    const int tx = tid & 15, ty = tid >> 4;   // ty 0..7 (8 m rows), tx 0..15 (8 n cols)

    for (int it = 0; it < 64; ++it) {
        int lin = it * 128 + tid;
        int n = lin >> 6, k = lin & 63;
        vhs[k * 128 + n] = Vh[(size_t)(n0 + n) * Hz + k0 + k];
    }

    const int e0 = bid * 512 + tid * 4;
    const int pm = e0 >> 10;
    const int pn = e0 & 1023;
    const int pnb = pn >> 7, pnl = pn & 127;

    float* partW = d_part + (size_t)bid * (64 * 128);
    unsigned target = 0;
    __syncthreads();

    for (int t = 0; t < Tz; ++t) {
        // prefetch g_t for phase 2 (independent of everything in phase 1)
        float4 s = __ldcg(reinterpret_cast<const float4*>(
            &d_g[((size_t)pm * Tz + t) * Hz + pn]));

        // ---- phase 1: stage h slice (coalesced float4, non-duplicated) ----
        {
            const float4* src = reinterpret_cast<const float4*>(d_hTr + (size_t)k0 * 64);
            float4* dst = reinterpret_cast<float4*>(hs);
#pragma unroll
            for (int r = 0; r < 8; ++r) {
                int i = r * 128 + tid;            // 0..1023 float4 index
                dst[i] = __ldcg(&src[i]);
            }
        }
        __syncthreads();

        // acc[p][j]: m-pair p covers rows (ty*8+2p, ty*8+2p+1), col j of 8
        ull acc[4][8];
#pragma unroll
        for (int p = 0; p < 4; ++p)
#pragma unroll
            for (int j = 0; j < 8; ++j) acc[p][j] = 0ull;

#pragma unroll 8
        for (int k = 0; k < 64; ++k) {
            ull a[4];
            lds2(a[0], a[1], saddr(&hs[k * 64 + ty * 8]));       // {m0,m1},{m2,m3}
            lds2(a[2], a[3], saddr(&hs[k * 64 + ty * 8 + 4]));   // {m4,m5},{m6,m7}
            float4 b0 = *reinterpret_cast<const float4*>(&vhs[k * 128 + tx * 4]);
            float4 b1 = *reinterpret_cast<const float4*>(&vhs[k * 128 + 64 + tx * 4]);
            ull bd[8];
            bd[0] = dup2(b0.x); bd[1] = dup2(b0.y); bd[2] = dup2(b0.z); bd[3] = dup2(b0.w);
            bd[4] = dup2(b1.x); bd[5] = dup2(b1.y); bd[6] = dup2(b1.z); bd[7] = dup2(b1.w);
#pragma unroll
            for (int p = 0; p < 4; ++p)
#pragma unroll
                for (int j = 0; j < 8; ++j)
                    ffma2(acc[p][j], a[p], bd[j]);
        }

        // write partials: unpack pair lanes -> two m rows, float4 stores
#pragma unroll
        for (int p = 0; p < 4; ++p) {
            int m0 = ty * 8 + 2 * p;
            float2 q0 = u2f(acc[p][0]), q1 = u2f(acc[p][1]);
            float2 q2 = u2f(acc[p][2]), q3 = u2f(acc[p][3]);
            float2 q4 = u2f(acc[p][4]), q5 = u2f(acc[p][5]);
            float2 q6 = u2f(acc[p][6]), q7 = u2f(acc[p][7]);
            __stcg(reinterpret_cast<float4*>(&partW[m0 * 128 + tx * 4]),
                   make_float4(q0.x, q1.x, q2.x, q3.x));
            __stcg(reinterpret_cast<float4*>(&partW[m0 * 128 + 64 + tx * 4]),
                   make_float4(q4.x, q5.x, q6.x, q7.x));
            __stcg(reinterpret_cast<float4*>(&partW[(m0 + 1) * 128 + tx * 4]),
                   make_float4(q0.y, q1.y, q2.y, q3.y));
            __stcg(reinterpret_cast<float4*>(&partW[(m0 + 1) * 128 + 64 + tx * 4]),
                   make_float4(q4.y, q5.y, q6.y, q7.y));
        }

        gsync(target);   // partials visible

        // ---- phase 2: reduce 16 partials + g_t, tanh, scatter h ----
#pragma unroll
        for (int k2 = 0; k2 < 16; ++k2) {
            float4 p = __ldcg(reinterpret_cast<const float4*>(
                &d_part[(size_t)(pnb * 16 + k2) * (64 * 128) + pm * 128 + pnl]));
            s.x += p.x; s.y += p.y; s.z += p.z; s.w += p.w;
        }
        float4 hv = make_float4(tanhf(s.x), tanhf(s.y), tanhf(s.z), tanhf(s.w));

        *reinterpret_cast<float4*>(&out[((size_t)pm * Tz + t) * Hz + pn]) = hv;
        __stcg(&d_hTr[(pn + 0) * 64 + pm], hv.x);
        __stcg(&d_hTr[(pn + 1) * 64 + pm], hv.y);
        __stcg(&d_hTr[(pn + 2) * 64 + pm], hv.z);
        __stcg(&d_hTr[(pn + 3) * 64 + pm], hv.w);
        if (t == Tz - 1) {
            *reinterpret_cast<float4*>(&outHT[(size_t)pm * Hz + pn]) = hv;
        }

        gsync(target);   // h ready for next step
    }
}

// ---------------- launch ----------------------------------------------------
extern "C" void kernel_launch(void* const* d_in, const int* in_sizes, int n_in,
                              void* d_out, int out_size) {
    const float* x  = (const float*)d_in[0];
    const float* h0 = (const float*)d_in[1];
    const float* c0 = (const float*)d_in[2];
    const float* Wx = (const float*)d_in[3];
    const float* bx = (const float*)d_in[4];
    const float* Uc = (const float*)d_in[5];
    const float* Vh = (const float*)d_in[6];

    float* out   = (float*)d_out;                       // [B,T,H]
    float* outHT = out + (size_t)Bz * Tz * Hz;          // [B,H]
    float* outCT = outHT + (size_t)Bz * Hz;             // [B,C]

    float *dxc, *dg;
    cudaGetSymbolAddress((void**)&dxc, d_xc);
    cudaGetSymbolAddress((void**)&dg, d_g);

    // 1) init: transpose h0, reset barrier
    init_kernel<<<(Hz * Bz + 255) / 256, 256>>>(h0);

    // 2) xc = x @ Wx^T + bx   (M=32768, N=512, K=1024)
    sgemm_tn<<<dim3((Bz * Tz) / 128, Cz / 128), 256>>>(x, Wx, bx, dxc, Cz, INz);

    // 3) EMA scan: xc -> c (in place), write c_T
    scan_kernel<<<(Bz * Cz) / 256, 256>>>(c0, outCT);

    // 4) g = c @ Uc^T   (M=32768, N=1024, K=512)
    sgemm_tn<<<dim3((Bz * Tz) / 128, Hz / 128), 256>>>(dxc, Uc, nullptr, dg, Hz, Cz);

    // 5) recurrence: h_t = tanh(g_t + h_{t-1} @ Vh^T), all 512 steps
    recur_kernel<<<RBLOCKS, RTHREADS>>>(Vh, out, outHT);
}

// round 9
// speedup vs baseline: 1.2707x; 1.0283x over previous
#include <cuda_runtime.h>
#include <math.h>
#include <stdint.h>

#define Bz 64
#define Tz 512
#define INz 1024
#define Hz 1024
#define Cz 512

#define RBLOCKS 128
#define RTHREADS 128

typedef unsigned long long ull;

// ---------------- persistent scratch ----------------------------------------
__device__ float d_xc[(size_t)Bz * Tz * Cz];          // xc, then c (in-place)
__device__ float d_g[(size_t)Bz * Tz * Hz];           // g = c @ Uc^T
__device__ float d_part[(size_t)RBLOCKS * 64 * 128];  // per-step partials
__device__ float d_hTr[Hz * 64];                      // h transposed [n][m]
__device__ unsigned d_gcount;                         // grid barrier counter

// ---------------- f32x2 helpers ---------------------------------------------
__device__ __forceinline__ uint32_t saddr(const void* p) {
    return (uint32_t)__cvta_generic_to_shared(p);
}
__device__ __forceinline__ void lds2(ull& a, ull& b, uint32_t addr) {
    asm volatile("ld.shared.v2.u64 {%0,%1}, [%2];" : "=l"(a), "=l"(b) : "r"(addr));
}
__device__ __forceinline__ void ffma2(ull& d, ull a, ull b) {
    asm("fma.rn.f32x2 %0, %1, %2, %0;" : "+l"(d) : "l"(a), "l"(b));
}
__device__ __forceinline__ float2 u2f(ull v) {
    float2 r; asm("mov.b64 {%0,%1}, %2;" : "=f"(r.x), "=f"(r.y) : "l"(v)); return r;
}
__device__ __forceinline__ ull dup2(float f) {
    ull d; asm("mov.b64 %0, {%1,%1};" : "=l"(d) : "f"(f)); return d;
}

// ---------------- init: transpose h0, reset barrier -------------------------
__global__ void init_kernel(const float* __restrict__ h0) {
    int idx = blockIdx.x * blockDim.x + threadIdx.x;   // 0 .. Hz*Bz-1
    if (idx == 0) d_gcount = 0u;
    if (idx < Hz * Bz) {
        int n = idx >> 6, m = idx & 63;
        d_hTr[n * 64 + m] = h0[m * Hz + n];
    }
}

// ---------------- EMA scan over T (in-place xc -> c), emit c_T --------------
__global__ void scan_kernel(const float* __restrict__ c0, float* __restrict__ outCT) {
    int idx = blockIdx.x * blockDim.x + threadIdx.x;   // 0 .. B*C-1
    int b = idx >> 9;
    int ch = idx & 511;
    float c = c0[idx];
    float* p = d_xc + (size_t)b * Tz * Cz + ch;
    const float a = 0.95f, na = 0.05f;
#pragma unroll 8
    for (int t = 0; t < Tz; ++t) {
        float v = p[t * Cz];
        c = na * c + a * v;
        p[t * Cz] = c;
    }
    outCT[idx] = c;
}

// ---------------- fp32x2 SGEMM: double-buffered, m-paired FFMA2 core --------
// C[M,N] = A[M,K] @ Bw[N,K]^T (+bias); 128x128 tile, 256 thr, 8x8/thread
__global__ __launch_bounds__(256, 2) void sgemm_tn(
    const float* __restrict__ A, const float* __restrict__ Bw,
    const float* __restrict__ bias, float* __restrict__ Cout,
    int N, int K)
{
    __shared__ float As[2][16][132];
    __shared__ float Bs[2][16][132];
    const int tid = threadIdx.x;
    const int tx = tid & 15, ty = tid >> 4;
    const int m0 = blockIdx.x * 128, n0 = blockIdx.y * 128;
    const int lrow = tid >> 2;
    const int lkq  = (tid & 3) << 2;

    const float* Aptr0 = &A[(size_t)(m0 + lrow) * K + lkq];
    const float* Aptr1 = &A[(size_t)(m0 + lrow + 64) * K + lkq];
    const float* Bptr0 = &Bw[(size_t)(n0 + lrow) * K + lkq];
    const float* Bptr1 = &Bw[(size_t)(n0 + lrow + 64) * K + lkq];

    // acc[p][j]: m-pair p (p0: ty*4+0/1, p1: ty*4+2/3, p2: 64+ty*4+0/1, p3: +2/3)
    ull acc[4][8];
#pragma unroll
    for (int p = 0; p < 4; ++p)
#pragma unroll
        for (int j = 0; j < 8; ++j) acc[p][j] = 0ull;

    {
        float4 va0 = *reinterpret_cast<const float4*>(Aptr0);
        float4 va1 = *reinterpret_cast<const float4*>(Aptr1);
        float4 vb0 = *reinterpret_cast<const float4*>(Bptr0);
        float4 vb1 = *reinterpret_cast<const float4*>(Bptr1);
        As[0][lkq + 0][lrow] = va0.x; As[0][lkq + 1][lrow] = va0.y;
        As[0][lkq + 2][lrow] = va0.z; As[0][lkq + 3][lrow] = va0.w;
        As[0][lkq + 0][lrow + 64] = va1.x; As[0][lkq + 1][lrow + 64] = va1.y;
        As[0][lkq + 2][lrow + 64] = va1.z; As[0][lkq + 3][lrow + 64] = va1.w;
        Bs[0][lkq + 0][lrow] = vb0.x; Bs[0][lkq + 1][lrow] = vb0.y;
        Bs[0][lkq + 2][lrow] = vb0.z; Bs[0][lkq + 3][lrow] = vb0.w;
        Bs[0][lkq + 0][lrow + 64] = vb1.x; Bs[0][lkq + 1][lrow + 64] = vb1.y;
        Bs[0][lkq + 2][lrow + 64] = vb1.z; Bs[0][lkq + 3][lrow + 64] = vb1.w;
    }
    __syncthreads();

    const int nchunk = K >> 4;
    for (int c = 0; c < nchunk; ++c) {
        const int cur = c & 1, nxt = cur ^ 1;
        float4 va0, va1, vb0, vb1;
        const bool more = (c + 1 < nchunk);
        if (more) {
            int off = (c + 1) * 16;
            va0 = *reinterpret_cast<const float4*>(Aptr0 + off);
            va1 = *reinterpret_cast<const float4*>(Aptr1 + off);
            vb0 = *reinterpret_cast<const float4*>(Bptr0 + off);
            vb1 = *reinterpret_cast<const float4*>(Bptr1 + off);
        }
#pragma unroll
        for (int k = 0; k < 16; ++k) {
            ull a[4];
            lds2(a[0], a[1], saddr(&As[cur][k][ty * 4]));        // {m0,m1},{m2,m3}
            lds2(a[2], a[3], saddr(&As[cur][k][ty * 4 + 64]));   // {m4,m5},{m6,m7}
            float4 b0 = *reinterpret_cast<const float4*>(&Bs[cur][k][tx * 4]);
            float4 b1 = *reinterpret_cast<const float4*>(&Bs[cur][k][tx * 4 + 64]);
            ull bd[8];
            bd[0] = dup2(b0.x); bd[1] = dup2(b0.y); bd[2] = dup2(b0.z); bd[3] = dup2(b0.w);
            bd[4] = dup2(b1.x); bd[5] = dup2(b1.y); bd[6] = dup2(b1.z); bd[7] = dup2(b1.w);
#pragma unroll
            for (int p = 0; p < 4; ++p)
#pragma unroll
                for (int j = 0; j < 8; ++j)
                    ffma2(acc[p][j], a[p], bd[j]);
        }
        if (more) {
            As[nxt][lkq + 0][lrow] = va0.x; As[nxt][lkq + 1][lrow] = va0.y;
            As[nxt][lkq + 2][lrow] = va0.z; As[nxt][lkq + 3][lrow] = va0.w;
            As[nxt][lkq + 0][lrow + 64] = va1.x; As[nxt][lkq + 1][lrow + 64] = va1.y;
            As[nxt][lkq + 2][lrow + 64] = va1.z; As[nxt][lkq + 3][lrow + 64] = va1.w;
            Bs[nxt][lkq + 0][lrow] = vb0.x; Bs[nxt][lkq + 1][lrow] = vb0.y;
            Bs[nxt][lkq + 2][lrow] = vb0.z; Bs[nxt][lkq + 3][lrow] = vb0.w;
            Bs[nxt][lkq + 0][lrow + 64] = vb1.x; Bs[nxt][lkq + 1][lrow + 64] = vb1.y;
            Bs[nxt][lkq + 2][lrow + 64] = vb1.z; Bs[nxt][lkq + 3][lrow + 64] = vb1.w;
        }
        __syncthreads();
    }

    float bv[8] = {0.f, 0.f, 0.f, 0.f, 0.f, 0.f, 0.f, 0.f};
    if (bias) {
#pragma unroll
        for (int j = 0; j < 4; ++j) {
            bv[j]     = bias[n0 + tx * 4 + j];
            bv[4 + j] = bias[n0 + 64 + tx * 4 + j];
        }
    }
    // unpack: pair p, lane 0 -> row base+0, lane 1 -> row base+1
#pragma unroll
    for (int p = 0; p < 4; ++p) {
        int rbase = m0 + ((p < 2) ? (ty * 4 + 2 * p) : (64 + ty * 4 + 2 * (p - 2)));
        float2 q0 = u2f(acc[p][0]), q1 = u2f(acc[p][1]);
        float2 q2 = u2f(acc[p][2]), q3 = u2f(acc[p][3]);
        float2 q4 = u2f(acc[p][4]), q5 = u2f(acc[p][5]);
        float2 q6 = u2f(acc[p][6]), q7 = u2f(acc[p][7]);
        *reinterpret_cast<float4*>(&Cout[(size_t)rbase * N + n0 + tx * 4]) =
            make_float4(q0.x + bv[0], q1.x + bv[1], q2.x + bv[2], q3.x + bv[3]);
        *reinterpret_cast<float4*>(&Cout[(size_t)rbase * N + n0 + 64 + tx * 4]) =
            make_float4(q4.x + bv[4], q5.x + bv[5], q6.x + bv[6], q7.x + bv[7]);
        *reinterpret_cast<float4*>(&Cout[(size_t)(rbase + 1) * N + n0 + tx * 4]) =
            make_float4(q0.y + bv[0], q1.y + bv[1], q2.y + bv[2], q3.y + bv[3]);
        *reinterpret_cast<float4*>(&Cout[(size_t)(rbase + 1) * N + n0 + 64 + tx * 4]) =
            make_float4(q4.y + bv[4], q5.y + bv[5], q6.y + bv[6], q7.y + bv[7]);
    }
}

// ---------------- grid-wide barrier (all 128 blocks co-resident) ------------
__device__ __forceinline__ void gsync(unsigned& target) {
    __threadfence();
    __syncthreads();
    target += RBLOCKS;
    if (threadIdx.x == 0) {
        atomicAdd(&d_gcount, 1u);
        while (*(volatile unsigned*)&d_gcount < target) { __nanosleep(32); }
    }
    __syncthreads();
}

// ---------------- persistent recurrence: m-paired FFMA2 core (R8 proven) ----
// grid 128 = 8 N-tiles (128 cols) x 16 K-slices (64), 128 threads/block
__global__ __launch_bounds__(RTHREADS, 1) void recur_kernel(
    const float* __restrict__ Vh, float* __restrict__ out, float* __restrict__ outHT)
{
    __shared__ float vhs[64 * 128];   // Vh slice [k][n] (32KB, resident all steps)
    __shared__ float hs[64 * 64];     // h slice  [k][m] (16KB, restaged per step)

    const int tid = threadIdx.x;
    const int bid = blockIdx.x;
    const int nb = bid >> 4, kb = bid & 15;
    const int n0 = nb * 128, k0 = kb * 64;
    const int tx = tid & 15, ty = tid >> 4;   // ty 0..7 (8 m rows), tx 0..15 (8 n cols)

    for (int it = 0; it < 64; ++it) {
        int lin = it * 128 + tid;
        int n = lin >> 6, k = lin & 63;
        vhs[k * 128 + n] = Vh[(size_t)(n0 + n) * Hz + k0 + k];
    }

    const int e0 = bid * 512 + tid * 4;
    const int pm = e0 >> 10;
    const int pn = e0 & 1023;
    const int pnb = pn >> 7, pnl = pn & 127;

    float* partW = d_part + (size_t)bid * (64 * 128);
    unsigned target = 0;
    __syncthreads();

    for (int t = 0; t < Tz; ++t) {
        // prefetch g_t for phase 2
        float4 s = __ldcg(reinterpret_cast<const float4*>(
            &d_g[((size_t)pm * Tz + t) * Hz + pn]));

        // ---- phase 1: stage h slice (coalesced float4) ----
        {
            const float4* src = reinterpret_cast<const float4*>(d_hTr + (size_t)k0 * 64);
            float4* dst = reinterpret_cast<float4*>(hs);
#pragma unroll
            for (int r = 0; r < 8; ++r) {
                int i = r * 128 + tid;
                dst[i] = __ldcg(&src[i]);
            }
        }
        __syncthreads();

        ull acc[4][8];
#pragma unroll
        for (int p = 0; p < 4; ++p)
#pragma unroll
            for (int j = 0; j < 8; ++j) acc[p][j] = 0ull;

#pragma unroll 8
        for (int k = 0; k < 64; ++k) {
            ull a[4];
            lds2(a[0], a[1], saddr(&hs[k * 64 + ty * 8]));
            lds2(a[2], a[3], saddr(&hs[k * 64 + ty * 8 + 4]));
            float4 b0 = *reinterpret_cast<const float4*>(&vhs[k * 128 + tx * 4]);
            float4 b1 = *reinterpret_cast<const float4*>(&vhs[k * 128 + 64 + tx * 4]);
            ull bd[8];
            bd[0] = dup2(b0.x); bd[1] = dup2(b0.y); bd[2] = dup2(b0.z); bd[3] = dup2(b0.w);
            bd[4] = dup2(b1.x); bd[5] = dup2(b1.y); bd[6] = dup2(b1.z); bd[7] = dup2(b1.w);
#pragma unroll
            for (int p = 0; p < 4; ++p)
#pragma unroll
                for (int j = 0; j < 8; ++j)
                    ffma2(acc[p][j], a[p], bd[j]);
        }

        // write partials: unpack pair lanes -> two m rows, float4 stores
#pragma unroll
        for (int p = 0; p < 4; ++p) {
            int m0 = ty * 8 + 2 * p;
            float2 q0 = u2f(acc[p][0]), q1 = u2f(acc[p][1]);
            float2 q2 = u2f(acc[p][2]), q3 = u2f(acc[p][3]);
            float2 q4 = u2f(acc[p][4]), q5 = u2f(acc[p][5]);
            float2 q6 = u2f(acc[p][6]), q7 = u2f(acc[p][7]);
            __stcg(reinterpret_cast<float4*>(&partW[m0 * 128 + tx * 4]),
                   make_float4(q0.x, q1.x, q2.x, q3.x));
            __stcg(reinterpret_cast<float4*>(&partW[m0 * 128 + 64 + tx * 4]),
                   make_float4(q4.x, q5.x, q6.x, q7.x));
            __stcg(reinterpret_cast<float4*>(&partW[(m0 + 1) * 128 + tx * 4]),
                   make_float4(q0.y, q1.y, q2.y, q3.y));
            __stcg(reinterpret_cast<float4*>(&partW[(m0 + 1) * 128 + 64 + tx * 4]),
                   make_float4(q4.y, q5.y, q6.y, q7.y));
        }

        gsync(target);   // partials visible

        // ---- phase 2: reduce 16 partials + g_t, tanh, scatter h ----
#pragma unroll
        for (int k2 = 0; k2 < 16; ++k2) {
            float4 p = __ldcg(reinterpret_cast<const float4*>(
                &d_part[(size_t)(pnb * 16 + k2) * (64 * 128) + pm * 128 + pnl]));
            s.x += p.x; s.y += p.y; s.z += p.z; s.w += p.w;
        }
        float4 hv = make_float4(tanhf(s.x), tanhf(s.y), tanhf(s.z), tanhf(s.w));

        *reinterpret_cast<float4*>(&out[((size_t)pm * Tz + t) * Hz + pn]) = hv;
        __stcg(&d_hTr[(pn + 0) * 64 + pm], hv.x);
        __stcg(&d_hTr[(pn + 1) * 64 + pm], hv.y);
        __stcg(&d_hTr[(pn + 2) * 64 + pm], hv.z);
        __stcg(&d_hTr[(pn + 3) * 64 + pm], hv.w);
        if (t == Tz - 1) {
            *reinterpret_cast<float4*>(&outHT[(size_t)pm * Hz + pn]) = hv;
        }

        gsync(target);   // h ready for next step
    }
}

// ---------------- launch ----------------------------------------------------
extern "C" void kernel_launch(void* const* d_in, const int* in_sizes, int n_in,
                              void* d_out, int out_size) {
    const float* x  = (const float*)d_in[0];
    const float* h0 = (const float*)d_in[1];
    const float* c0 = (const float*)d_in[2];
    const float* Wx = (const float*)d_in[3];
    const float* bx = (const float*)d_in[4];
    const float* Uc = (const float*)d_in[5];
    const float* Vh = (const float*)d_in[6];

    float* out   = (float*)d_out;                       // [B,T,H]
    float* outHT = out + (size_t)Bz * Tz * Hz;          // [B,H]
    float* outCT = outHT + (size_t)Bz * Hz;             // [B,C]

    float *dxc, *dg;
    cudaGetSymbolAddress((void**)&dxc, d_xc);
    cudaGetSymbolAddress((void**)&dg, d_g);

    // 1) init: transpose h0, reset barrier
    init_kernel<<<(Hz * Bz + 255) / 256, 256>>>(h0);

    // 2) xc = x @ Wx^T + bx   (M=32768, N=512, K=1024)
    sgemm_tn<<<dim3((Bz * Tz) / 128, Cz / 128), 256>>>(x, Wx, bx, dxc, Cz, INz);

    // 3) EMA scan: xc -> c (in place), write c_T
    scan_kernel<<<(Bz * Cz) / 256, 256>>>(c0, outCT);

    // 4) g = c @ Uc^T   (M=32768, N=1024, K=512)
    sgemm_tn<<<dim3((Bz * Tz) / 128, Hz / 128), 256>>>(dxc, Uc, nullptr, dg, Hz, Cz);

    // 5) recurrence: h_t = tanh(g_t + h_{t-1} @ Vh^T), all 512 steps
    recur_kernel<<<RBLOCKS, RTHREADS>>>(Vh, out, outHT);
}